// round 7
// baseline (speedup 1.0000x reference)
#include <cuda_runtime.h>
#include <cuda_fp16.h>
#include <cstdint>

// Problem dims (fixed)
#define N_IMG   8
#define C_IN    2048
#define HW      4096
#define C_OUT   512
#define M_TOTAL (N_IMG * HW)      // 32768

// GEMM tiling
#define BM 128
#define BN 128
#define BK 64
#define KT (C_IN / BK)            // 32
#define STAGES 3
#define A_STAGE_BYTES 16384       // 64 k-rows x 256B (128 halfs of m)
#define STAGE_BYTES   32768       // + 16KB B (128 n-rows x 128B)
#define SMEM_DYN (STAGES * STAGE_BYTES)   // 98304

// Weight center taps as fp16, [o][c]
__device__ __half g_B[C_OUT * C_IN];

// ---------------- pre-pass ----------------
__global__ void extract_w_kernel(const float* __restrict__ W) {
    int i4 = (blockIdx.x * 256 + threadIdx.x) * 4;   // over C_OUT*C_IN, 4/thread
    __half h[4];
#pragma unroll
    for (int i = 0; i < 4; i++)
        h[i] = __float2half(W[(size_t)(i4 + i) * 9 + 4]);
    *reinterpret_cast<uint2*>(&g_B[i4]) = *reinterpret_cast<uint2*>(h);
}

// ---------------- helpers ----------------
__device__ __forceinline__ uint32_t smem_u32(const void* p) {
    uint32_t a;
    asm("{ .reg .u64 t; cvta.to.shared.u64 t, %1; cvt.u32.u64 %0, t; }" : "=r"(a) : "l"(p));
    return a;
}
__device__ __forceinline__ void cp16(uint32_t s, const void* g) {
    asm volatile("cp.async.cg.shared.global [%0], [%1], 16;" :: "r"(s), "l"(g));
}
#define CP_COMMIT() asm volatile("cp.async.commit_group;" ::: "memory")
#define CP_WAIT1()  asm volatile("cp.async.wait_group 1;" ::: "memory")
#define CP_WAIT0()  asm volatile("cp.async.wait_group 0;" ::: "memory")

__device__ __forceinline__ void sts128(uint32_t addr, uint32_t r0, uint32_t r1,
                                       uint32_t r2, uint32_t r3) {
    asm volatile("st.shared.v4.b32 [%0], {%1,%2,%3,%4};"
                 :: "r"(addr), "r"(r0), "r"(r1), "r"(r2), "r"(r3) : "memory");
}
__device__ __forceinline__ void ldsm_x4(uint32_t& r0, uint32_t& r1, uint32_t& r2, uint32_t& r3,
                                        uint32_t addr) {
    asm volatile("ldmatrix.sync.aligned.m8n8.x4.shared.b16 {%0,%1,%2,%3}, [%4];"
                 : "=r"(r0), "=r"(r1), "=r"(r2), "=r"(r3) : "r"(addr));
}
__device__ __forceinline__ void ldsm_x4_t(uint32_t& r0, uint32_t& r1, uint32_t& r2, uint32_t& r3,
                                          uint32_t addr) {
    asm volatile("ldmatrix.sync.aligned.m8n8.x4.trans.shared.b16 {%0,%1,%2,%3}, [%4];"
                 : "=r"(r0), "=r"(r1), "=r"(r2), "=r"(r3) : "r"(addr));
}
__device__ __forceinline__ void mma16816(float* c, const uint32_t* a, const uint32_t* b) {
    asm volatile(
        "mma.sync.aligned.m16n8k16.row.col.f32.f16.f16.f32 "
        "{%0,%1,%2,%3}, {%4,%5,%6,%7}, {%8,%9}, {%0,%1,%2,%3};"
        : "+f"(c[0]), "+f"(c[1]), "+f"(c[2]), "+f"(c[3])
        : "r"(a[0]), "r"(a[1]), "r"(a[2]), "r"(a[3]), "r"(b[0]), "r"(b[1]));
}
__device__ __forceinline__ void cvt_sts(uint32_t addr, const float4& v0, const float4& v1) {
    __half2 h0 = __floats2half2_rn(v0.x, v0.y);
    __half2 h1 = __floats2half2_rn(v0.z, v0.w);
    __half2 h2 = __floats2half2_rn(v1.x, v1.y);
    __half2 h3 = __floats2half2_rn(v1.z, v1.w);
    sts128(addr, *reinterpret_cast<uint32_t*>(&h0), *reinterpret_cast<uint32_t*>(&h1),
                 *reinterpret_cast<uint32_t*>(&h2), *reinterpret_cast<uint32_t*>(&h3));
}

// ---------------- GEMM: 128 threads = 4 warps, warp tile 64x64 ----------------
// A (fp32) loaded from fea, converted to fp16 in-register, STS'd at the TOP of
// each iter (short live range, no spills); B via cp.async.
__global__ void __launch_bounds__(128, 2)
gemm_kernel(const float* __restrict__ fea, const float* __restrict__ bias,
            float* __restrict__ out) {
    extern __shared__ char smem[];
    const uint32_t sb = smem_u32(smem);

    const int tid  = threadIdx.x;
    const int lane = tid & 31;
    const int wid  = tid >> 5;
    const int wm   = wid & 1;           // m-warp: offset wm*64
    const int wn   = wid >> 1;          // n-warp: offset wn*64
    const int ntile = blockIdx.x;       // 0..3
    const int mtile = blockIdx.y;       // 0..255

    const int m0   = mtile * BM;
    const int nimg = m0 >> 12;
    const int p0   = m0 & (HW - 1);

    // ---- A global-load addressing ----
    const int arow0 = tid >> 4;         // k-row base (stride 8 per j)
    const int ahc   = tid & 15;         // 16B chunk in 256B row
    const float* aSrc = fea + (size_t)nimg * C_IN * HW + (size_t)arow0 * HW + p0 + ahc * 8;
    const uint32_t aSts0 = (uint32_t)(arow0 * 256 + ((ahc ^ (arow0 & 7)) << 4)); // +j*2048

    // ---- B cp.async addressing ----
    const int brow0 = tid >> 3;
    const int bhc   = tid & 7;
    const __half* bSrc = g_B + (size_t)(ntile * BN + brow0) * C_IN + bhc * 8;
    const uint32_t bSts0 = (uint32_t)(A_STAGE_BYTES + brow0 * 128
                                      + ((bhc ^ (brow0 & 7)) << 4));             // +j*2048

    // ---- ldmatrix lane addressing ----
    const int grp = lane >> 3, lr8 = lane & 7;
    const int krl   = (grp >> 1) * 8 + lr8;
    const int ac16b = wm * 8 + (grp & 1);
    const int nrl   = (grp >> 1) * 8 + lr8;
    uint32_t aOff[4];
#pragma unroll
    for (int mb = 0; mb < 4; mb++)
        aOff[mb] = (uint32_t)(krl * 256 + (((ac16b + 2 * mb) ^ (krl & 7)) << 4));

    float acc[4][8][4];
#pragma unroll
    for (int i = 0; i < 4; i++)
#pragma unroll
        for (int j = 0; j < 8; j++)
#pragma unroll
            for (int q = 0; q < 4; q++) acc[i][j][q] = 0.f;

    // ---- prologue: stages 0,1 (A synchronous, B async) ----
#pragma unroll
    for (int s = 0; s < 2; s++) {
        const uint32_t st = sb + s * STAGE_BYTES;
        const float* ap = aSrc + (size_t)s * BK * HW;
#pragma unroll
        for (int j = 0; j < 8; j++) {
            float4 v0 = *reinterpret_cast<const float4*>(ap + (size_t)j * 8 * HW);
            float4 v1 = *reinterpret_cast<const float4*>(ap + (size_t)j * 8 * HW + 4);
            cvt_sts(st + aSts0 + j * 2048, v0, v1);
        }
#pragma unroll
        for (int j = 0; j < 8; j++)
            cp16(st + bSts0 + j * 2048, bSrc + s * BK + j * 16 * C_IN);
        CP_COMMIT();
    }

    for (int kt = 0; kt < KT; kt++) {
        if (kt < KT - 1) { CP_WAIT1(); } else { CP_WAIT0(); }
        __syncthreads();

        // ---- produce tile kt+2 NOW into slot (kt+2)%3 == (kt-1)%3 (freed by
        //      the sync above). Two 4-j half-batches cap live fp32 regs at 32.
        if (kt + 2 < KT) {
            const uint32_t st = sb + ((kt + 2) % STAGES) * STAGE_BYTES;
            const float* ap = aSrc + (size_t)(kt + 2) * BK * HW;
#pragma unroll
            for (int h = 0; h < 2; h++) {
                float4 v0[4], v1[4];
#pragma unroll
                for (int j = 0; j < 4; j++) {
                    const float* app = ap + (size_t)(h * 4 + j) * 8 * HW;
                    v0[j] = *reinterpret_cast<const float4*>(app);
                    v1[j] = *reinterpret_cast<const float4*>(app + 4);
                }
#pragma unroll
                for (int j = 0; j < 4; j++)
                    cvt_sts(st + aSts0 + (h * 4 + j) * 2048, v0[j], v1[j]);
            }
#pragma unroll
            for (int j = 0; j < 8; j++)
                cp16(st + bSts0 + j * 2048, bSrc + (kt + 2) * BK + j * 16 * C_IN);
            CP_COMMIT();
        }

        // ---- compute stage kt%3 ----
        const uint32_t base = sb + (kt % STAGES) * STAGE_BYTES;
#pragma unroll
        for (int ks = 0; ks < 4; ks++) {
            uint32_t aF[4][4], bF[8][2];
#pragma unroll
            for (int mb = 0; mb < 4; mb++)
                ldsm_x4_t(aF[mb][0], aF[mb][1], aF[mb][2], aF[mb][3],
                          base + aOff[mb] + (uint32_t)(ks * 4096));
#pragma unroll
            for (int nbp = 0; nbp < 4; nbp++) {
                const int nrow = wn * 64 + nbp * 16 + nrl;
                const uint32_t ba = base + (uint32_t)(A_STAGE_BYTES + nrow * 128
                                   + (((ks * 2 + (grp & 1)) ^ (nrow & 7)) << 4));
                ldsm_x4(bF[2 * nbp][0], bF[2 * nbp][1], bF[2 * nbp + 1][0], bF[2 * nbp + 1][1], ba);
            }
#pragma unroll
            for (int mb = 0; mb < 4; mb++)
#pragma unroll
                for (int nb = 0; nb < 8; nb++)
                    mma16816(acc[mb][nb], aF[mb], bF[nb]);
        }
    }

    // ---- epilogue: bias + relu, direct STG ----
    const int lr = lane >> 2;
    const int lc = (lane & 3) * 2;
    const int oBase = ntile * BN + wn * 64 + lc;
    const int pBase = p0 + wm * 64 + lr;
    float* outN = out + (size_t)nimg * C_OUT * HW;

#pragma unroll
    for (int nb = 0; nb < 8; nb++) {
        const int o = oBase + nb * 8;
        const float b0 = bias[o], b1 = bias[o + 1];
        float* r0p = outN + (size_t)o * HW;
        float* r1p = outN + (size_t)(o + 1) * HW;
#pragma unroll
        for (int mb = 0; mb < 4; mb++) {
            const int p = pBase + mb * 16;
            float v0 = acc[mb][nb][0] + b0;
            float v1 = acc[mb][nb][1] + b1;
            float v2 = acc[mb][nb][2] + b0;
            float v3 = acc[mb][nb][3] + b1;
            r0p[p]     = v0 > 0.f ? v0 : 0.f;
            r1p[p]     = v1 > 0.f ? v1 : 0.f;
            r0p[p + 8] = v2 > 0.f ? v2 : 0.f;
            r1p[p + 8] = v3 > 0.f ? v3 : 0.f;
        }
    }
}

// ---------------- launch ----------------
extern "C" void kernel_launch(void* const* d_in, const int* in_sizes, int n_in,
                              void* d_out, int out_size) {
    const float* fea = (const float*)d_in[0];
    const float* W   = (const float*)d_in[1];
    const float* b   = (const float*)d_in[2];
    float* out       = (float*)d_out;

    cudaFuncSetAttribute(gemm_kernel, cudaFuncAttributeMaxDynamicSharedMemorySize, SMEM_DYN);

    extract_w_kernel<<<(C_OUT * C_IN) / 1024, 256>>>(W);
    // ntile fastest so the 4 CTAs sharing an A m-tile co-run -> L2 dedup of fp32 A
    gemm_kernel<<<dim3(C_OUT / BN, M_TOTAL / BM), 128, SMEM_DYN>>>(fea, b, out);
}

// round 8
// speedup vs baseline: 1.0771x; 1.0771x over previous
#include <cuda_runtime.h>
#include <cuda_fp16.h>
#include <cstdint>

// Problem dims (fixed)
#define N_IMG   8
#define C_IN    2048
#define HW      4096
#define C_OUT   512
#define M_TOTAL (N_IMG * HW)      // 32768

// GEMM tiling
#define BM 128
#define BN 128
#define BK 64
#define KT (C_IN / BK)            // 32
#define STAGES 3
#define A_STAGE_BYTES 16384       // 64 k-rows x 256B (128 halfs of m)
#define STAGE_BYTES   32768       // + 16KB B (128 n-rows x 128B)
#define SMEM_DYN (STAGES * STAGE_BYTES)   // 98304

// Weight center taps as fp16, [o][c]
__device__ __half g_B[C_OUT * C_IN];

// ---------------- pre-pass ----------------
__global__ void extract_w_kernel(const float* __restrict__ W) {
    int i4 = (blockIdx.x * 256 + threadIdx.x) * 4;   // over C_OUT*C_IN, 4/thread
    __half h[4];
#pragma unroll
    for (int i = 0; i < 4; i++)
        h[i] = __float2half(W[(size_t)(i4 + i) * 9 + 4]);
    *reinterpret_cast<uint2*>(&g_B[i4]) = *reinterpret_cast<uint2*>(h);
}

// ---------------- helpers ----------------
__device__ __forceinline__ uint32_t smem_u32(const void* p) {
    uint32_t a;
    asm("{ .reg .u64 t; cvta.to.shared.u64 t, %1; cvt.u32.u64 %0, t; }" : "=r"(a) : "l"(p));
    return a;
}
__device__ __forceinline__ void cp16(uint32_t s, const void* g) {
    asm volatile("cp.async.cg.shared.global [%0], [%1], 16;" :: "r"(s), "l"(g));
}
#define CP_COMMIT() asm volatile("cp.async.commit_group;" ::: "memory")
#define CP_WAIT1()  asm volatile("cp.async.wait_group 1;" ::: "memory")
#define CP_WAIT0()  asm volatile("cp.async.wait_group 0;" ::: "memory")

__device__ __forceinline__ void sts128(uint32_t addr, uint32_t r0, uint32_t r1,
                                       uint32_t r2, uint32_t r3) {
    asm volatile("st.shared.v4.b32 [%0], {%1,%2,%3,%4};"
                 :: "r"(addr), "r"(r0), "r"(r1), "r"(r2), "r"(r3) : "memory");
}
__device__ __forceinline__ void ldsm_x4(uint32_t& r0, uint32_t& r1, uint32_t& r2, uint32_t& r3,
                                        uint32_t addr) {
    asm volatile("ldmatrix.sync.aligned.m8n8.x4.shared.b16 {%0,%1,%2,%3}, [%4];"
                 : "=r"(r0), "=r"(r1), "=r"(r2), "=r"(r3) : "r"(addr));
}
__device__ __forceinline__ void ldsm_x4_t(uint32_t& r0, uint32_t& r1, uint32_t& r2, uint32_t& r3,
                                          uint32_t addr) {
    asm volatile("ldmatrix.sync.aligned.m8n8.x4.trans.shared.b16 {%0,%1,%2,%3}, [%4];"
                 : "=r"(r0), "=r"(r1), "=r"(r2), "=r"(r3) : "r"(addr));
}
__device__ __forceinline__ void mma16816(float* c, const uint32_t* a, const uint32_t* b) {
    asm volatile(
        "mma.sync.aligned.m16n8k16.row.col.f32.f16.f16.f32 "
        "{%0,%1,%2,%3}, {%4,%5,%6,%7}, {%8,%9}, {%0,%1,%2,%3};"
        : "+f"(c[0]), "+f"(c[1]), "+f"(c[2]), "+f"(c[3])
        : "r"(a[0]), "r"(a[1]), "r"(a[2]), "r"(a[3]), "r"(b[0]), "r"(b[1]));
}
__device__ __forceinline__ void cvt_sts(uint32_t addr, const float4& v0, const float4& v1) {
    __half2 h0 = __floats2half2_rn(v0.x, v0.y);
    __half2 h1 = __floats2half2_rn(v0.z, v0.w);
    __half2 h2 = __floats2half2_rn(v1.x, v1.y);
    __half2 h3 = __floats2half2_rn(v1.z, v1.w);
    sts128(addr, *reinterpret_cast<uint32_t*>(&h0), *reinterpret_cast<uint32_t*>(&h1),
                 *reinterpret_cast<uint32_t*>(&h2), *reinterpret_cast<uint32_t*>(&h3));
}

// ---------------- GEMM: 128 threads = 4 warps, warp tile 64x64 ----------------
// A (fp32) from fea: LDGs issued BEFORE each compute half-block (latency hidden
// under MMAs), cvt+STS after — only 32 fp32 regs held across compute.
__global__ void __launch_bounds__(128, 2)
gemm_kernel(const float* __restrict__ fea, const float* __restrict__ bias,
            float* __restrict__ out) {
    extern __shared__ char smem[];
    const uint32_t sb = smem_u32(smem);

    const int tid  = threadIdx.x;
    const int lane = tid & 31;
    const int wid  = tid >> 5;
    const int wm   = wid & 1;           // m-warp: offset wm*64
    const int wn   = wid >> 1;          // n-warp: offset wn*64
    const int ntile = blockIdx.x;       // 0..3
    const int mtile = blockIdx.y;       // 0..255

    const int m0   = mtile * BM;
    const int nimg = m0 >> 12;
    const int p0   = m0 & (HW - 1);

    // ---- A global-load addressing ----
    const int arow0 = tid >> 4;         // k-row base (stride 8 per j)
    const int ahc   = tid & 15;         // 16B chunk in 256B row
    const float* aSrc = fea + (size_t)nimg * C_IN * HW + (size_t)arow0 * HW + p0 + ahc * 8;
    const uint32_t aSts0 = (uint32_t)(arow0 * 256 + ((ahc ^ (arow0 & 7)) << 4)); // +j*2048

    // ---- B cp.async addressing ----
    const int brow0 = tid >> 3;
    const int bhc   = tid & 7;
    const __half* bSrc = g_B + (size_t)(ntile * BN + brow0) * C_IN + bhc * 8;
    const uint32_t bSts0 = (uint32_t)(A_STAGE_BYTES + brow0 * 128
                                      + ((bhc ^ (brow0 & 7)) << 4));             // +j*2048

    // ---- ldmatrix lane addressing ----
    const int grp = lane >> 3, lr8 = lane & 7;
    const int krl   = (grp >> 1) * 8 + lr8;
    const int ac16b = wm * 8 + (grp & 1);
    const int nrl   = (grp >> 1) * 8 + lr8;
    uint32_t aOff[4];
#pragma unroll
    for (int mb = 0; mb < 4; mb++)
        aOff[mb] = (uint32_t)(krl * 256 + (((ac16b + 2 * mb) ^ (krl & 7)) << 4));

    float acc[4][8][4];
#pragma unroll
    for (int i = 0; i < 4; i++)
#pragma unroll
        for (int j = 0; j < 8; j++)
#pragma unroll
            for (int q = 0; q < 4; q++) acc[i][j][q] = 0.f;

    // ---- prologue: stages 0,1 (A synchronous, B async) ----
#pragma unroll
    for (int s = 0; s < 2; s++) {
        const uint32_t st = sb + s * STAGE_BYTES;
        const float* ap = aSrc + (size_t)s * BK * HW;
#pragma unroll
        for (int j = 0; j < 8; j++) {
            float4 v0 = *reinterpret_cast<const float4*>(ap + (size_t)j * 8 * HW);
            float4 v1 = *reinterpret_cast<const float4*>(ap + (size_t)j * 8 * HW + 4);
            cvt_sts(st + aSts0 + j * 2048, v0, v1);
        }
#pragma unroll
        for (int j = 0; j < 8; j++)
            cp16(st + bSts0 + j * 2048, bSrc + s * BK + j * 16 * C_IN);
        CP_COMMIT();
    }

    for (int kt = 0; kt < KT; kt++) {
        if (kt < KT - 1) { CP_WAIT1(); } else { CP_WAIT0(); }
        __syncthreads();

        const bool pf = (kt + 2 < KT);
        const uint32_t st = sb + ((kt + 2) % STAGES) * STAGE_BYTES;   // == (kt-1)%3, freed
        const float* ap = aSrc + (size_t)(kt + 2) * BK * HW;
        const uint32_t base = sb + (kt % STAGES) * STAGE_BYTES;

        // B prefetch: async, zero register cost — issue immediately
        if (pf) {
#pragma unroll
            for (int j = 0; j < 8; j++)
                cp16(st + bSts0 + j * 2048, bSrc + (kt + 2) * BK + j * 16 * C_IN);
        }

        // A batch 0: issue LDGs j=0..3, consume after compute half 0
        float4 v0[4], v1[4];
        if (pf) {
#pragma unroll
            for (int j = 0; j < 4; j++) {
                const float* app = ap + (size_t)j * 8 * HW;
                v0[j] = *reinterpret_cast<const float4*>(app);
                v1[j] = *reinterpret_cast<const float4*>(app + 4);
            }
        }

#pragma unroll
        for (int ks = 0; ks < 4; ks++) {
            // ---- compute ks ----
            {
                uint32_t aF[4][4], bF[8][2];
#pragma unroll
                for (int mb = 0; mb < 4; mb++)
                    ldsm_x4_t(aF[mb][0], aF[mb][1], aF[mb][2], aF[mb][3],
                              base + aOff[mb] + (uint32_t)(ks * 4096));
#pragma unroll
                for (int nbp = 0; nbp < 4; nbp++) {
                    const int nrow = wn * 64 + nbp * 16 + nrl;
                    const uint32_t ba = base + (uint32_t)(A_STAGE_BYTES + nrow * 128
                                       + (((ks * 2 + (grp & 1)) ^ (nrow & 7)) << 4));
                    ldsm_x4(bF[2 * nbp][0], bF[2 * nbp][1],
                            bF[2 * nbp + 1][0], bF[2 * nbp + 1][1], ba);
                }
#pragma unroll
                for (int mb = 0; mb < 4; mb++)
#pragma unroll
                    for (int nb = 0; nb < 8; nb++)
                        mma16816(acc[mb][nb], aF[mb], bF[nb]);
            }
            // after half 0: store batch 0, issue batch 1 LDGs
            if (ks == 1 && pf) {
#pragma unroll
                for (int j = 0; j < 4; j++)
                    cvt_sts(st + aSts0 + j * 2048, v0[j], v1[j]);
#pragma unroll
                for (int j = 0; j < 4; j++) {
                    const float* app = ap + (size_t)(4 + j) * 8 * HW;
                    v0[j] = *reinterpret_cast<const float4*>(app);
                    v1[j] = *reinterpret_cast<const float4*>(app + 4);
                }
            }
        }

        // after half 1: store batch 1, commit the stage's group
        if (pf) {
#pragma unroll
            for (int j = 0; j < 4; j++)
                cvt_sts(st + aSts0 + (4 + j) * 2048, v0[j], v1[j]);
            CP_COMMIT();
        }
    }

    // ---- epilogue: bias + relu, direct STG ----
    const int lr = lane >> 2;
    const int lc = (lane & 3) * 2;
    const int oBase = ntile * BN + wn * 64 + lc;
    const int pBase = p0 + wm * 64 + lr;
    float* outN = out + (size_t)nimg * C_OUT * HW;

#pragma unroll
    for (int nb = 0; nb < 8; nb++) {
        const int o = oBase + nb * 8;
        const float b0 = bias[o], b1 = bias[o + 1];
        float* r0p = outN + (size_t)o * HW;
        float* r1p = outN + (size_t)(o + 1) * HW;
#pragma unroll
        for (int mb = 0; mb < 4; mb++) {
            const int p = pBase + mb * 16;
            float v0f = acc[mb][nb][0] + b0;
            float v1f = acc[mb][nb][1] + b1;
            float v2f = acc[mb][nb][2] + b0;
            float v3f = acc[mb][nb][3] + b1;
            r0p[p]     = v0f > 0.f ? v0f : 0.f;
            r1p[p]     = v1f > 0.f ? v1f : 0.f;
            r0p[p + 8] = v2f > 0.f ? v2f : 0.f;
            r1p[p + 8] = v3f > 0.f ? v3f : 0.f;
        }
    }
}

// ---------------- launch ----------------
extern "C" void kernel_launch(void* const* d_in, const int* in_sizes, int n_in,
                              void* d_out, int out_size) {
    const float* fea = (const float*)d_in[0];
    const float* W   = (const float*)d_in[1];
    const float* b   = (const float*)d_in[2];
    float* out       = (float*)d_out;

    cudaFuncSetAttribute(gemm_kernel, cudaFuncAttributeMaxDynamicSharedMemorySize, SMEM_DYN);

    extract_w_kernel<<<(C_OUT * C_IN) / 1024, 256>>>(W);
    // ntile fastest so the 4 CTAs sharing an A m-tile co-run -> L2 dedup of fp32 A
    gemm_kernel<<<dim3(C_OUT / BN, M_TOTAL / BM), 128, SMEM_DYN>>>(fea, b, out);
}

// round 9
// speedup vs baseline: 1.0966x; 1.0181x over previous
#include <cuda_runtime.h>
#include <cuda_fp16.h>
#include <cstdint>

// Problem dims (fixed)
#define N_IMG   8
#define C_IN    2048
#define HW      4096
#define C_OUT   512
#define M_TOTAL (N_IMG * HW)      // 32768

// GEMM tiling: one fat CTA 128(m) x 256(n), 256 threads, warp tile 64x64
#define BM 128
#define BN 256
#define BK 64
#define KT (C_IN / BK)            // 32
#define STAGES 3
#define A_STAGE_BYTES 16384       // 64 k-rows x 256B (128 halfs of m)
#define B_STAGE_BYTES 32768       // 256 n-rows x 128B (64 halfs of k)
#define STAGE_BYTES   49152
#define SMEM_DYN (STAGES * STAGE_BYTES)   // 147456

// Weight center taps as fp16, [o][c]
__device__ __half g_B[C_OUT * C_IN];

// ---------------- pre-pass ----------------
__global__ void extract_w_kernel(const float* __restrict__ W) {
    int i4 = (blockIdx.x * 256 + threadIdx.x) * 4;   // over C_OUT*C_IN, 4/thread
    __half h[4];
#pragma unroll
    for (int i = 0; i < 4; i++)
        h[i] = __float2half(W[(size_t)(i4 + i) * 9 + 4]);
    *reinterpret_cast<uint2*>(&g_B[i4]) = *reinterpret_cast<uint2*>(h);
}

// ---------------- helpers ----------------
__device__ __forceinline__ uint32_t smem_u32(const void* p) {
    uint32_t a;
    asm("{ .reg .u64 t; cvta.to.shared.u64 t, %1; cvt.u32.u64 %0, t; }" : "=r"(a) : "l"(p));
    return a;
}
__device__ __forceinline__ void cp16(uint32_t s, const void* g) {
    asm volatile("cp.async.cg.shared.global [%0], [%1], 16;" :: "r"(s), "l"(g));
}
#define CP_COMMIT() asm volatile("cp.async.commit_group;" ::: "memory")
#define CP_WAIT1()  asm volatile("cp.async.wait_group 1;" ::: "memory")
#define CP_WAIT0()  asm volatile("cp.async.wait_group 0;" ::: "memory")

__device__ __forceinline__ void sts128(uint32_t addr, uint32_t r0, uint32_t r1,
                                       uint32_t r2, uint32_t r3) {
    asm volatile("st.shared.v4.b32 [%0], {%1,%2,%3,%4};"
                 :: "r"(addr), "r"(r0), "r"(r1), "r"(r2), "r"(r3) : "memory");
}
__device__ __forceinline__ void ldsm_x4(uint32_t& r0, uint32_t& r1, uint32_t& r2, uint32_t& r3,
                                        uint32_t addr) {
    asm volatile("ldmatrix.sync.aligned.m8n8.x4.shared.b16 {%0,%1,%2,%3}, [%4];"
                 : "=r"(r0), "=r"(r1), "=r"(r2), "=r"(r3) : "r"(addr));
}
__device__ __forceinline__ void ldsm_x4_t(uint32_t& r0, uint32_t& r1, uint32_t& r2, uint32_t& r3,
                                          uint32_t addr) {
    asm volatile("ldmatrix.sync.aligned.m8n8.x4.trans.shared.b16 {%0,%1,%2,%3}, [%4];"
                 : "=r"(r0), "=r"(r1), "=r"(r2), "=r"(r3) : "r"(addr));
}
__device__ __forceinline__ void mma16816(float* c, const uint32_t* a, const uint32_t* b) {
    asm volatile(
        "mma.sync.aligned.m16n8k16.row.col.f32.f16.f16.f32 "
        "{%0,%1,%2,%3}, {%4,%5,%6,%7}, {%8,%9}, {%0,%1,%2,%3};"
        : "+f"(c[0]), "+f"(c[1]), "+f"(c[2]), "+f"(c[3])
        : "r"(a[0]), "r"(a[1]), "r"(a[2]), "r"(a[3]), "r"(b[0]), "r"(b[1]));
}
__device__ __forceinline__ void cvt_sts(uint32_t addr, const float4& v0, const float4& v1) {
    __half2 h0 = __floats2half2_rn(v0.x, v0.y);
    __half2 h1 = __floats2half2_rn(v0.z, v0.w);
    __half2 h2 = __floats2half2_rn(v1.x, v1.y);
    __half2 h3 = __floats2half2_rn(v1.z, v1.w);
    sts128(addr, *reinterpret_cast<uint32_t*>(&h0), *reinterpret_cast<uint32_t*>(&h1),
                 *reinterpret_cast<uint32_t*>(&h2), *reinterpret_cast<uint32_t*>(&h3));
}

// ---------------- GEMM: 256 threads = 8 warps (2m x 4n), warp tile 64x64 ----
// R6-proven schedule: after barrier -> B cp.async + all A LDGs issued, then the
// full MMA block, then A cvt+STS. A fp32 loaded ONCE per SM (one fat CTA).
__global__ void __launch_bounds__(256, 1)
gemm_kernel(const float* __restrict__ fea, const float* __restrict__ bias,
            float* __restrict__ out) {
    extern __shared__ char smem[];
    const uint32_t sb = smem_u32(smem);

    const int tid  = threadIdx.x;
    const int lane = tid & 31;
    const int wid  = tid >> 5;
    const int wm   = wid & 1;           // m-warp: offset wm*64
    const int wn   = wid >> 1;          // n-warp: offset wn*64 (0..3)
    const int ntile = blockIdx.x;       // 0..1
    const int mtile = blockIdx.y;       // 0..255

    const int m0   = mtile * BM;
    const int nimg = m0 >> 12;
    const int p0   = m0 & (HW - 1);

    // ---- A global-load addressing: 32KB fp32 tile over 256 threads ----
    // row = (tid>>4) + 16*j (j=0..3), chunk = (tid&15)*32B of the 512B fp32 row
    const int arow0 = tid >> 4;         // 0..15
    const int ahc   = tid & 15;
    const float* aSrc = fea + (size_t)nimg * C_IN * HW + (size_t)arow0 * HW + p0 + ahc * 8;
    const uint32_t aSts0 = (uint32_t)(arow0 * 256 + ((ahc ^ (arow0 & 7)) << 4)); // +j*4096

    // ---- B cp.async addressing: 32KB over 256 threads, 8 chunks each ----
    const int brow0 = tid >> 3;         // 0..31, +32 per j (j=0..7)
    const int bhc   = tid & 7;
    const __half* bSrc = g_B + (size_t)(ntile * BN + brow0) * C_IN + bhc * 8;
    const uint32_t bSts0 = (uint32_t)(A_STAGE_BYTES + brow0 * 128
                                      + ((bhc ^ (brow0 & 7)) << 4));             // +j*4096

    // ---- ldmatrix lane addressing ----
    const int grp = lane >> 3, lr8 = lane & 7;
    const int krl   = (grp >> 1) * 8 + lr8;
    const int ac16b = wm * 8 + (grp & 1);
    const int nrl   = (grp >> 1) * 8 + lr8;
    uint32_t aOff[4];
#pragma unroll
    for (int mb = 0; mb < 4; mb++)
        aOff[mb] = (uint32_t)(krl * 256 + (((ac16b + 2 * mb) ^ (krl & 7)) << 4));

    float acc[4][8][4];
#pragma unroll
    for (int i = 0; i < 4; i++)
#pragma unroll
        for (int j = 0; j < 8; j++)
#pragma unroll
            for (int q = 0; q < 4; q++) acc[i][j][q] = 0.f;

    // ---- prologue: stages 0,1 (A synchronous, B async) ----
#pragma unroll
    for (int s = 0; s < 2; s++) {
        const uint32_t st = sb + s * STAGE_BYTES;
        const float* ap = aSrc + (size_t)s * BK * HW;
#pragma unroll
        for (int j = 0; j < 4; j++) {
            float4 v0 = *reinterpret_cast<const float4*>(ap + (size_t)j * 16 * HW);
            float4 v1 = *reinterpret_cast<const float4*>(ap + (size_t)j * 16 * HW + 4);
            cvt_sts(st + aSts0 + j * 4096, v0, v1);
        }
#pragma unroll
        for (int j = 0; j < 8; j++)
            cp16(st + bSts0 + j * 4096, bSrc + s * BK + (size_t)j * 32 * C_IN);
        CP_COMMIT();
    }

    for (int kt = 0; kt < KT; kt++) {
        if (kt < KT - 1) { CP_WAIT1(); } else { CP_WAIT0(); }
        __syncthreads();

        const bool pf = (kt + 2 < KT);
        const uint32_t st = sb + ((kt + 2) % STAGES) * STAGE_BYTES;   // == (kt-1)%3, freed
        const uint32_t base = sb + (kt % STAGES) * STAGE_BYTES;

        // B prefetch: async, committed immediately
        if (pf) {
#pragma unroll
            for (int j = 0; j < 8; j++)
                cp16(st + bSts0 + j * 4096, bSrc + (kt + 2) * BK + (size_t)j * 32 * C_IN);
            CP_COMMIT();
        }

        // A fp32 LDGs for tile kt+2: issue all now, consume after compute (R6 schedule)
        float4 v0[4], v1[4];
        if (pf) {
            const float* ap = aSrc + (size_t)(kt + 2) * BK * HW;
#pragma unroll
            for (int j = 0; j < 4; j++) {
                v0[j] = *reinterpret_cast<const float4*>(ap + (size_t)j * 16 * HW);
                v1[j] = *reinterpret_cast<const float4*>(ap + (size_t)j * 16 * HW + 4);
            }
        }

        // ---- compute stage kt%3 ----
#pragma unroll
        for (int ks = 0; ks < 4; ks++) {
            uint32_t aF[4][4], bF[8][2];
#pragma unroll
            for (int mb = 0; mb < 4; mb++)
                ldsm_x4_t(aF[mb][0], aF[mb][1], aF[mb][2], aF[mb][3],
                          base + aOff[mb] + (uint32_t)(ks * 4096));
#pragma unroll
            for (int nbp = 0; nbp < 4; nbp++) {
                const int nrow = wn * 64 + nbp * 16 + nrl;
                const uint32_t ba = base + (uint32_t)(A_STAGE_BYTES + nrow * 128
                                   + (((ks * 2 + (grp & 1)) ^ (nrow & 7)) << 4));
                ldsm_x4(bF[2 * nbp][0], bF[2 * nbp][1],
                        bF[2 * nbp + 1][0], bF[2 * nbp + 1][1], ba);
            }
#pragma unroll
            for (int mb = 0; mb < 4; mb++)
#pragma unroll
                for (int nb = 0; nb < 8; nb++)
                    mma16816(acc[mb][nb], aF[mb], bF[nb]);
        }

        // ---- store A tile kt+2 ----
        if (pf) {
#pragma unroll
            for (int j = 0; j < 4; j++)
                cvt_sts(st + aSts0 + j * 4096, v0[j], v1[j]);
        }
    }

    // ---- epilogue: bias + relu, direct STG ----
    const int lr = lane >> 2;
    const int lc = (lane & 3) * 2;
    const int oBase = ntile * BN + wn * 64 + lc;
    const int pBase = p0 + wm * 64 + lr;
    float* outN = out + (size_t)nimg * C_OUT * HW;

#pragma unroll
    for (int nb = 0; nb < 8; nb++) {
        const int o = oBase + nb * 8;
        const float b0 = bias[o], b1 = bias[o + 1];
        float* r0p = outN + (size_t)o * HW;
        float* r1p = outN + (size_t)(o + 1) * HW;
#pragma unroll
        for (int mb = 0; mb < 4; mb++) {
            const int p = pBase + mb * 16;
            float v0f = acc[mb][nb][0] + b0;
            float v1f = acc[mb][nb][1] + b1;
            float v2f = acc[mb][nb][2] + b0;
            float v3f = acc[mb][nb][3] + b1;
            r0p[p]     = v0f > 0.f ? v0f : 0.f;
            r1p[p]     = v1f > 0.f ? v1f : 0.f;
            r0p[p + 8] = v2f > 0.f ? v2f : 0.f;
            r1p[p + 8] = v3f > 0.f ? v3f : 0.f;
        }
    }
}

// ---------------- launch ----------------
extern "C" void kernel_launch(void* const* d_in, const int* in_sizes, int n_in,
                              void* d_out, int out_size) {
    const float* fea = (const float*)d_in[0];
    const float* W   = (const float*)d_in[1];
    const float* b   = (const float*)d_in[2];
    float* out       = (float*)d_out;

    cudaFuncSetAttribute(gemm_kernel, cudaFuncAttributeMaxDynamicSharedMemorySize, SMEM_DYN);

    extract_w_kernel<<<(C_OUT * C_IN) / 1024, 256>>>(W);
    // ntile fastest so the 2 CTAs sharing an A m-tile co-run -> L2 dedup of fp32 A
    gemm_kernel<<<dim3(C_OUT / BN, M_TOTAL / BM), 256, SMEM_DYN>>>(fea, b, out);
}